// round 6
// baseline (speedup 1.0000x reference)
#include <cuda_runtime.h>
#include <cstdint>

#define B_SZ   32
#define RESN   100
#define ITERS  1000
#define KSPLIT 16         // fc4 k-dim split (k-chunk = 32)

typedef unsigned long long ull;

// -------- scratch (device globals; no allocation allowed) ----------
__device__ float g_h1[B_SZ * 128];
__device__ float g_h2[B_SZ * 256];
__device__ float g_h3[B_SZ * 512];
__device__ float g_part[KSPLIT * B_SZ * 10000];   // fc4 partial sums

// ---------------------- f32x2 helpers (FFMA2) ----------------------
__device__ __forceinline__ ull pack2(float lo, float hi) {
    ull r; unsigned a = __float_as_uint(lo), b = __float_as_uint(hi);
    asm("mov.b64 %0, {%1,%2};" : "=l"(r) : "r"(a), "r"(b));
    return r;
}
__device__ __forceinline__ float lo2(ull v) {
    unsigned a, b;
    asm("mov.b64 {%0,%1}, %2;" : "=r"(a), "=r"(b) : "l"(v));
    return __uint_as_float(a);
}
__device__ __forceinline__ float hi2(ull v) {
    unsigned a, b;
    asm("mov.b64 {%0,%1}, %2;" : "=r"(a), "=r"(b) : "l"(v));
    return __uint_as_float(b);
}
// (hi(a), lo(b)) — the "shifted" pair for W/E stencil operands
__device__ __forceinline__ ull shift_pair(ull a, ull b) {
    unsigned a0, a1, b0, b1;
    asm("mov.b64 {%0,%1}, %2;" : "=r"(a0), "=r"(a1) : "l"(a));
    asm("mov.b64 {%0,%1}, %2;" : "=r"(b0), "=r"(b1) : "l"(b));
    ull r;
    asm("mov.b64 %0, {%1,%2};" : "=l"(r) : "r"(a1), "r"(b0));
    return r;
}
__device__ __forceinline__ ull fma2(ull a, ull b, ull c) {
    ull d;
    asm("fma.rn.f32x2 %0, %1, %2, %3;" : "=l"(d) : "l"(a), "l"(b), "l"(c));
    return d;
}
__device__ __forceinline__ ull mul2(ull a, ull b) {
    ull d;
    asm("mul.rn.f32x2 %0, %1, %2;" : "=l"(d) : "l"(a), "l"(b));
    return d;
}

// -------------------- MLP layers 1..3 (small) ----------------------
__global__ void fc1_kernel(const float* __restrict__ pores,
                           const float* __restrict__ W,
                           const float* __restrict__ bias) {
    int idx = blockIdx.x * blockDim.x + threadIdx.x;
    if (idx >= B_SZ * 128) return;
    int b = idx >> 7, j = idx & 127;
    float acc = bias[j];
#pragma unroll
    for (int k = 0; k < 25; k++)
        acc = fmaf(pores[b * 25 + k], W[k * 128 + j], acc);
    g_h1[idx] = fmaxf(acc, 0.0f);
}

__global__ void fc2_kernel(const float* __restrict__ W,
                           const float* __restrict__ bias) {
    int idx = blockIdx.x * blockDim.x + threadIdx.x;
    if (idx >= B_SZ * 256) return;
    int b = idx >> 8, j = idx & 255;
    float acc = bias[j];
#pragma unroll 8
    for (int k = 0; k < 128; k++)
        acc = fmaf(g_h1[b * 128 + k], W[k * 256 + j], acc);
    g_h2[idx] = fmaxf(acc, 0.0f);
}

__global__ void fc3_kernel(const float* __restrict__ W,
                           const float* __restrict__ bias) {
    int idx = blockIdx.x * blockDim.x + threadIdx.x;
    if (idx >= B_SZ * 512) return;
    int b = idx >> 9, j = idx & 511;
    float acc = bias[j];
#pragma unroll 8
    for (int k = 0; k < 256; k++)
        acc = fmaf(g_h2[b * 256 + k], W[k * 512 + j], acc);
    g_h3[idx] = fmaxf(acc, 0.0f);
}

// ---------------- fc4 stage 1: split-K partial sums ----------------
__global__ __launch_bounds__(128) void fc4_partial_kernel(
    const float* __restrict__ W)     // [512,10000]
{
    __shared__ float h3s[B_SZ * 32];
    int k0 = blockIdx.y * 32;
    for (int i = threadIdx.x; i < B_SZ * 32; i += blockDim.x) {
        int q = i >> 5, kk = i & 31;
        h3s[i] = g_h3[q * 512 + k0 + kk];
    }
    __syncthreads();

    int o = blockIdx.x * blockDim.x + threadIdx.x;
    if (o >= RESN * RESN) return;

    float acc[B_SZ];
#pragma unroll
    for (int q = 0; q < B_SZ; q++) acc[q] = 0.0f;

#pragma unroll
    for (int kk = 0; kk < 32; kk += 4) {
        float w0 = W[(k0 + kk + 0) * 10000 + o];
        float w1 = W[(k0 + kk + 1) * 10000 + o];
        float w2 = W[(k0 + kk + 2) * 10000 + o];
        float w3 = W[(k0 + kk + 3) * 10000 + o];
#pragma unroll
        for (int q = 0; q < B_SZ; q++) {
            acc[q] = fmaf(h3s[q * 32 + kk + 0], w0, acc[q]);
            acc[q] = fmaf(h3s[q * 32 + kk + 1], w1, acc[q]);
            acc[q] = fmaf(h3s[q * 32 + kk + 2], w2, acc[q]);
            acc[q] = fmaf(h3s[q * 32 + kk + 3], w3, acc[q]);
        }
    }

    float* dst = g_part + blockIdx.y * (B_SZ * 10000);
#pragma unroll
    for (int q = 0; q < B_SZ; q++)
        dst[q * 10000 + o] = acc[q];
}

// -------- fc4 stage 2: reduce + bias + residual + clamp ------------
__global__ __launch_bounds__(128) void fc4_final_kernel(
    const float* __restrict__ bias,  // [10000]
    const float* __restrict__ pores, // [32,25]
    float* __restrict__ cond)        // [32,10000]
{
    int o = blockIdx.x * blockDim.x + threadIdx.x;
    if (o >= RESN * RESN) return;
    int i = o / RESN, j = o % RESN;
    int pidx = (i / 20) * 5 + (j / 20);
    float bb = bias[o];
    int q0 = blockIdx.y * 4;
#pragma unroll
    for (int qq = 0; qq < 4; qq++) {
        int q = q0 + qq;
        float s = bb;
#pragma unroll
        for (int p = 0; p < KSPLIT; p++)
            s += g_part[p * (B_SZ * 10000) + q * 10000 + o];
        float base = 1.0f - pores[q * 25 + pidx];
        cond[q * 10000 + o] = fmaxf(s + base, 0.01f);
    }
}

// ------------- Jacobi: R1 layout + packed f32x2 math ----------------
// One CTA per sample, 512 threads (500 active). Thread (r = tid%100,
// s = tid/100) owns row r, cols [20s, 20s+20) as 10 packed f32x2 pairs.
// T double-buffered in SMEM; N/S rows loaded as ulonglong2 (2 pairs per
// 16B). Stencil via fma.rn.f32x2: 40 FFMA2 instead of 80 FFMA per iter.
__global__ __launch_bounds__(512, 1)
void jacobi_kernel(const float* __restrict__ cond,   // [32,10000]
                   float* __restrict__ kappa)        // [32]
{
    extern __shared__ float sm[];
    float* Ta = sm;               // 10000
    float* Tb = sm + 10000;       // 10000
    float* partial = sm + 20000;  // 5

    int b = blockIdx.x;
    const float* k = cond + b * 10000;
    int tid = threadIdx.x;
    bool act = tid < 500;
    int r  = tid % 100;
    int s  = tid / 100;
    int c0 = s * 20;

    const ull ONE2  = 0x3F8000003F800000ULL;   // (1.0f, 1.0f)
    const ull ZERO2 = 0ULL;

    ull cN[10], cS[10], cW[10], cE[10], P[10];

    if (act) {
        int rm = (r == 0)  ? 0  : r - 1;
        int rp = (r == 99) ? 99 : r + 1;
        float fN[20], fS[20], fW[20], fE[20];
#pragma unroll
        for (int j = 0; j < 20; j++) {
            int c  = c0 + j;
            int cm = (c == 0)  ? 0  : c - 1;
            int cp = (c == 99) ? 99 : c + 1;
            float kc = k[r * 100 + c];
            float kn = 0.5f * (kc + k[rm * 100 + c]);
            float ks = 0.5f * (kc + k[rp * 100 + c]);
            float kw = 0.5f * (kc + k[r * 100 + cm]);
            float ke = 0.5f * (kc + k[r * 100 + cp]);
            float inv = 1.0f / (kn + ks + kw + ke + 1e-12f);
            fN[j] = kn * inv; fS[j] = ks * inv;
            fW[j] = kw * inv; fE[j] = ke * inv;
        }
#pragma unroll
        for (int m = 0; m < 10; m++) {
            cN[m] = pack2(fN[2*m], fN[2*m+1]);
            cS[m] = pack2(fS[2*m], fS[2*m+1]);
            cW[m] = pack2(fW[2*m], fW[2*m+1]);
            cE[m] = pack2(fE[2*m], fE[2*m+1]);
        }
        float tv = 1.0f - (float)r * (1.0f / 99.0f);
        ull tv2 = pack2(tv, tv);
#pragma unroll
        for (int m = 0; m < 10; m++) P[m] = tv2;
        ulonglong2* irow = reinterpret_cast<ulonglong2*>(Ta + r * 100 + c0);
#pragma unroll
        for (int mm = 0; mm < 5; mm++) {
            ulonglong2 v; v.x = tv2; v.y = tv2;
            irow[mm] = v;
        }
    }
    __syncthreads();

    float* cur = Ta;
    float* nxt = Tb;

    for (int it = 0; it < ITERS; ++it) {
        if (act) {
            int base = r * 100 + c0;
            float left   = (s == 0) ? lo2(P[0]) : cur[base - 1];
            float rightb = (s == 4) ? hi2(P[9]) : cur[base + 20];
            // clamped addresses: boundary rows read own row, value overridden
            const ulonglong2* nrow = reinterpret_cast<const ulonglong2*>(
                cur + ((r == 0)  ? base : base - 100));
            const ulonglong2* srow = reinterpret_cast<const ulonglong2*>(
                cur + ((r == 99) ? base : base + 100));
            ulonglong2* orow = reinterpret_cast<ulonglong2*>(nxt + base);

            ull Scur = pack2(left, lo2(P[0]));   // S_0
#pragma unroll
            for (int mm = 0; mm < 5; mm++) {
                ulonglong2 nv = nrow[mm];
                ulonglong2 sv = srow[mm];
                if (r == 0)  { nv.x = ONE2;  nv.y = ONE2;  }
                if (r == 99) { sv.x = ZERO2; sv.y = ZERO2; }

                // pair m = 2mm
                {
                    int m = 2 * mm;
                    ull Snext = shift_pair(P[m], P[m + 1]);          // S_{m+1}
                    ull t = mul2(cE[m], Snext);
                    t = fma2(cW[m], Scur, t);
                    t = fma2(cS[m], sv.x, t);
                    P[m] = fma2(cN[m], nv.x, t);
                    Scur = Snext;
                }
                // pair m = 2mm+1
                {
                    int m = 2 * mm + 1;
                    ull Snext = (m == 9) ? pack2(hi2(P[9]), rightb)
                                         : shift_pair(P[m], P[m + 1]);
                    ull t = mul2(cE[m], Snext);
                    t = fma2(cW[m], Scur, t);
                    t = fma2(cS[m], sv.y, t);
                    P[m] = fma2(cN[m], nv.y, t);
                    Scur = Snext;
                }
                ulonglong2 ov; ov.x = P[2 * mm]; ov.y = P[2 * mm + 1];
                orow[mm] = ov;
            }
        }
        __syncthreads();
        float* t = cur; cur = nxt; nxt = t;
    }

    // kappa = 2 * sum_c k[0,c] * (1 - T[0,c])
    if (act && r == 0) {
        float p = 0.0f;
#pragma unroll
        for (int m = 0; m < 10; m++) {
            p += k[c0 + 2*m]     * (1.0f - lo2(P[m]));
            p += k[c0 + 2*m + 1] * (1.0f - hi2(P[m]));
        }
        partial[s] = p;
    }
    __syncthreads();
    if (tid == 0)
        kappa[b] = 2.0f * (partial[0] + partial[1] + partial[2] + partial[3] + partial[4]);
}

// --------------------------- launcher ------------------------------
extern "C" void kernel_launch(void* const* d_in, const int* in_sizes, int n_in,
                              void* d_out, int out_size) {
    const float* pores = (const float*)d_in[0];
    const float* W1 = (const float*)d_in[1];
    const float* b1 = (const float*)d_in[2];
    const float* W2 = (const float*)d_in[3];
    const float* b2 = (const float*)d_in[4];
    const float* W3 = (const float*)d_in[5];
    const float* b3 = (const float*)d_in[6];
    const float* W4 = (const float*)d_in[7];
    const float* b4 = (const float*)d_in[8];

    float* out   = (float*)d_out;
    float* kappa = out;          // [32]
    float* cond  = out + B_SZ;   // [32,100,100]

    const int SMEM_JAC = (2 * 10000 + 8) * sizeof(float);  // ~80 KB
    cudaFuncSetAttribute(jacobi_kernel, cudaFuncAttributeMaxDynamicSharedMemorySize, SMEM_JAC);

    fc1_kernel<<<(B_SZ * 128 + 255) / 256, 256>>>(pores, W1, b1);
    fc2_kernel<<<(B_SZ * 256 + 255) / 256, 256>>>(W2, b2);
    fc3_kernel<<<(B_SZ * 512 + 255) / 256, 256>>>(W3, b3);
    dim3 g4((10000 + 127) / 128, KSPLIT);
    fc4_partial_kernel<<<g4, 128>>>(W4);
    dim3 g5((10000 + 127) / 128, B_SZ / 4);
    fc4_final_kernel<<<g5, 128>>>(b4, pores, cond);
    jacobi_kernel<<<B_SZ, 512, SMEM_JAC>>>(cond, kappa);
}